// round 2
// baseline (speedup 1.0000x reference)
#include <cuda_runtime.h>

// DWT Haar L1 loss, fully fused single kernel:
//   loss = (2/N) * sum over 2x2 blocks of |a+b+c+d|+|a+b-c-d|+|a-b+c-d|+|a-b-c+d|
// with (a,b,c,d) = pred - target at the 4 block positions. Pure streaming
// reduction; final cross-block reduction done by the last block to finish
// (ticket counter), so no separate zero/reduce kernel launch.

#define NBLOCKS 1184   // 148 SMs x 8 CTAs (256 thr, <=32 regs) = exactly 1 wave

__device__ float        g_partials[NBLOCKS];
__device__ unsigned int g_ticket = 0;   // reset by last block each launch

__global__ void __launch_bounds__(256, 8)
dwt_loss_kernel(const float* __restrict__ pred,
                const float* __restrict__ target,
                float* __restrict__ out,
                int nwork, float scale)
{
    float acc = 0.0f;
    const int stride = gridDim.x * blockDim.x;

    for (int i = blockIdx.x * blockDim.x + threadIdx.x; i < nwork; i += stride) {
        // One work item = one float4 from row 2r and row 2r+1 of both tensors
        // (row = 512 floats, so a row-pair spans 1024).
        int pair = i >> 7;
        int xv   = i & 127;
        size_t base = (size_t)pair * 1024 + (size_t)xv * 4;

        float4 p0 = __ldcs(reinterpret_cast<const float4*>(pred   + base));
        float4 p1 = __ldcs(reinterpret_cast<const float4*>(pred   + base + 512));
        float4 t0 = __ldcs(reinterpret_cast<const float4*>(target + base));
        float4 t1 = __ldcs(reinterpret_cast<const float4*>(target + base + 512));

        // Block 0: columns {x, y}
        float a = p0.x - t0.x;
        float b = p0.y - t0.y;
        float c = p1.x - t1.x;
        float d = p1.y - t1.y;
        float s0 = a + b, s1 = c + d, d0 = a - b, d1 = c - d;
        acc += fabsf(s0 + s1) + fabsf(s0 - s1) + fabsf(d0 + d1) + fabsf(d0 - d1);

        // Block 1: columns {z, w}
        a = p0.z - t0.z;
        b = p0.w - t0.w;
        c = p1.z - t1.z;
        d = p1.w - t1.w;
        s0 = a + b; s1 = c + d; d0 = a - b; d1 = c - d;
        acc += fabsf(s0 + s1) + fabsf(s0 - s1) + fabsf(d0 + d1) + fabsf(d0 - d1);
    }

    // ---- intra-block reduction ----
    #pragma unroll
    for (int o = 16; o > 0; o >>= 1)
        acc += __shfl_down_sync(0xffffffffu, acc, o);

    __shared__ float smem[8];
    __shared__ bool  s_last;
    int lane = threadIdx.x & 31;
    int wid  = threadIdx.x >> 5;
    if (lane == 0) smem[wid] = acc;
    __syncthreads();

    if (wid == 0) {
        acc = (lane < 8) ? smem[lane] : 0.0f;
        #pragma unroll
        for (int o = 4; o > 0; o >>= 1)
            acc += __shfl_down_sync(0xffffffffu, acc, o);
        if (lane == 0) {
            g_partials[blockIdx.x] = acc;
            __threadfence();
            unsigned int t = atomicAdd(&g_ticket, 1u);
            s_last = (t == (unsigned int)(gridDim.x - 1));
        }
    }
    __syncthreads();

    // ---- last block to finish reduces all partials ----
    if (s_last) {
        __threadfence();
        float v = 0.0f;
        for (int i = threadIdx.x; i < NBLOCKS; i += 256)
            v += g_partials[i];
        #pragma unroll
        for (int o = 16; o > 0; o >>= 1)
            v += __shfl_down_sync(0xffffffffu, v, o);
        if (lane == 0) smem[wid] = v;
        __syncthreads();
        if (wid == 0) {
            v = (lane < 8) ? smem[lane] : 0.0f;
            #pragma unroll
            for (int o = 4; o > 0; o >>= 1)
                v += __shfl_down_sync(0xffffffffu, v, o);
            if (lane == 0) {
                out[0] = v * scale;
                g_ticket = 0;   // reset for next graph replay (deterministic)
            }
        }
    }
}

extern "C" void kernel_launch(void* const* d_in, const int* in_sizes, int n_in,
                              void* d_out, int out_size)
{
    const float* pred   = (const float*)d_in[0];
    const float* target = (const float*)d_in[1];
    float* out = (float*)d_out;

    const int total = in_sizes[0];          // 32*3*512*512 = 25,165,824
    const int nwork = total / 8;            // 8 elems of each tensor per item
    const float scale = 2.0f / (float)total;

    dwt_loss_kernel<<<NBLOCKS, 256>>>(pred, target, out, nwork, scale);
}